// round 2
// baseline (speedup 1.0000x reference)
#include <cuda_runtime.h>
#include <math.h>

// Problem capacities (fixed by the dataset: N=100000, E=1600000)
#define NMAX 100096
#define EMAX 1600000

// -------- scratch (alloc-free: __device__ globals) --------
__device__ float g_a[NMAX * 64];       // node scores (tanh(x Wa^T + ba))
__device__ float g_v[NMAX * 64];       // node values (tanh(x Wv^T + bv))
__device__ float g_h1[NMAX * 64];      // layer-1 output
__device__ float g_ex[EMAX];           // exp(edge logit), CSR order
__device__ int   g_rowptr[NMAX + 1];
__device__ int   g_cnt[NMAX];
__device__ int   g_srcc[EMAX];
__device__ int   g_dstc[EMAX];

// -------------------- CSR build --------------------
__global__ void k_zero_cnt(int N) {
    int i = blockIdx.x * blockDim.x + threadIdx.x;
    if (i < N) g_cnt[i] = 0;
}

__global__ void k_count(const int* __restrict__ src, int E) {
    int e = blockIdx.x * blockDim.x + threadIdx.x;
    if (e < E) atomicAdd(&g_cnt[src[e]], 1);
}

// single-block exclusive scan of g_cnt -> g_rowptr, zeroes g_cnt as it goes
__global__ void k_scan(int N, int E) {
    __shared__ int sh[1024];
    int t = threadIdx.x;
    int chunk = (N + 1023) / 1024;
    int start = t * chunk;
    int end = min(start + chunk, N);
    int s = 0;
    for (int i = start; i < end; i++) s += g_cnt[i];
    sh[t] = s;
    __syncthreads();
    for (int off = 1; off < 1024; off <<= 1) {
        int v = 0;
        if (t >= off) v = sh[t - off];
        __syncthreads();
        if (t >= off) sh[t] += v;
        __syncthreads();
    }
    int run = (t == 0) ? 0 : sh[t - 1];
    for (int i = start; i < end; i++) {
        int c = g_cnt[i];
        g_rowptr[i] = run;
        g_cnt[i] = 0;
        run += c;
    }
    if (t == 1023) g_rowptr[N] = sh[1023];  // == E
}

__global__ void k_scatter(const int* __restrict__ src, const int* __restrict__ dst, int E) {
    int e = blockIdx.x * blockDim.x + threadIdx.x;
    if (e < E) {
        int s = src[e];
        int p = g_rowptr[s] + atomicAdd(&g_cnt[s], 1);
        g_srcc[p] = s;
        g_dstc[p] = dst[e];
    }
}

// -------------------- GEMM: Out[N,64] = tanh(X[N,K] @ W[64,K]^T + b) --------------------
#define BM 64
#define BN 64
#define BK 16
#define XPAD 4

__global__ __launch_bounds__(256) void k_gemm(
    const float* __restrict__ X, int N, int K,
    const float* __restrict__ W, const float* __restrict__ b,
    float* __restrict__ Out)
{
    __shared__ __align__(16) float Xs[BK][BM + XPAD];
    __shared__ __align__(16) float Ws[BK][BN + XPAD];
    int tid = threadIdx.x;
    int bm = blockIdx.x * BM;
    int tr = tid / 16;       // 0..15
    int tc = tid % 16;       // 0..15
    int lm = tid / 4;        // 0..63  row (X) / out index (W)
    int lk4 = (tid % 4) * 4; // 0,4,8,12

    float c[4][4] = {};

    for (int k0 = 0; k0 < K; k0 += BK) {
        // load X tile (guard rows)
        {
            int gm = bm + lm;
            float4 v = make_float4(0.f, 0.f, 0.f, 0.f);
            if (gm < N) v = *(const float4*)&X[(size_t)gm * K + k0 + lk4];
            Xs[lk4 + 0][lm] = v.x;
            Xs[lk4 + 1][lm] = v.y;
            Xs[lk4 + 2][lm] = v.z;
            Xs[lk4 + 3][lm] = v.w;
        }
        // load W tile
        {
            float4 v = *(const float4*)&W[(size_t)lm * K + k0 + lk4];
            Ws[lk4 + 0][lm] = v.x;
            Ws[lk4 + 1][lm] = v.y;
            Ws[lk4 + 2][lm] = v.z;
            Ws[lk4 + 3][lm] = v.w;
        }
        __syncthreads();
        #pragma unroll
        for (int k = 0; k < BK; k++) {
            float a0[4], b0[4];
            #pragma unroll
            for (int i = 0; i < 4; i++) a0[i] = Xs[k][tr * 4 + i];
            #pragma unroll
            for (int j = 0; j < 4; j++) b0[j] = Ws[k][tc * 4 + j];
            #pragma unroll
            for (int i = 0; i < 4; i++)
                #pragma unroll
                for (int j = 0; j < 4; j++)
                    c[i][j] = fmaf(a0[i], b0[j], c[i][j]);
        }
        __syncthreads();
    }

    #pragma unroll
    for (int i = 0; i < 4; i++) {
        int gm = bm + tr * 4 + i;
        if (gm < N) {
            #pragma unroll
            for (int j = 0; j < 4; j++) {
                int jj = tc * 4 + j;
                Out[(size_t)gm * 64 + jj] = tanhf(c[i][j] + b[jj]);
            }
        }
    }
}

// -------------------- edge logits: g_ex[p] = exp(tanh((a[s]+a[d]) . We + be)) --------------------
__global__ __launch_bounds__(256) void k_edge(
    const float* __restrict__ We, const float* __restrict__ be, int E)
{
    int gt = blockIdx.x * blockDim.x + threadIdx.x;
    int p = gt >> 4;
    int l = gt & 15;
    if (p >= E) return;
    int s = g_srcc[p];
    int d = g_dstc[p];
    const float4* a4 = (const float4*)g_a;
    float4 xa = a4[(size_t)s * 16 + l];
    float4 xd = a4[(size_t)d * 16 + l];
    float4 w = ((const float4*)We)[l];
    float sum = (xa.x + xd.x) * w.x + (xa.y + xd.y) * w.y +
                (xa.z + xd.z) * w.z + (xa.w + xd.w) * w.w;
    sum += __shfl_xor_sync(0xffffffffu, sum, 8);
    sum += __shfl_xor_sync(0xffffffffu, sum, 4);
    sum += __shfl_xor_sync(0xffffffffu, sum, 2);
    sum += __shfl_xor_sync(0xffffffffu, sum, 1);
    if (l == 0) {
        float e = tanhf(sum + be[0]);
        g_ex[p] = expf(e);  // |e|<1 so no max-subtraction needed
    }
}

// -------------------- aggregation + row std-normalization (warp per node) --------------------
__global__ __launch_bounds__(256) void k_agg(float* __restrict__ Out, int N)
{
    int wid = (blockIdx.x * blockDim.x + threadIdx.x) >> 5;
    int lane = threadIdx.x & 31;
    if (wid >= N) return;

    int r0 = g_rowptr[wid];
    int r1 = g_rowptr[wid + 1];

    // softmax denominator
    float sum = 0.f;
    for (int p = r0 + lane; p < r1; p += 32) sum += g_ex[p];
    #pragma unroll
    for (int off = 16; off > 0; off >>= 1) sum += __shfl_xor_sync(0xffffffffu, sum, off);
    float inv = 1.0f / sum;

    float acc0 = 0.f, acc1 = 0.f;
    for (int base = r0; base < r1; base += 32) {
        int p = base + lane;
        float att = 0.f;
        int d = 0;
        if (p < r1) {
            att = g_ex[p] * inv;
            d = g_dstc[p];
        }
        int cnt = min(32, r1 - base);
        #pragma unroll 4
        for (int j = 0; j < cnt; j++) {
            float aj = __shfl_sync(0xffffffffu, att, j);
            int dj = __shfl_sync(0xffffffffu, d, j);
            acc0 = fmaf(aj, g_v[(size_t)dj * 64 + lane], acc0);
            acc1 = fmaf(aj, g_v[(size_t)dj * 64 + lane + 32], acc1);
        }
    }

    // mean, then unbiased std over the 64 values
    float s = acc0 + acc1;
    #pragma unroll
    for (int off = 16; off > 0; off >>= 1) s += __shfl_xor_sync(0xffffffffu, s, off);
    float mean = s * (1.0f / 64.0f);
    float d0 = acc0 - mean, d1 = acc1 - mean;
    float q = d0 * d0 + d1 * d1;
    #pragma unroll
    for (int off = 16; off > 0; off >>= 1) q += __shfl_xor_sync(0xffffffffu, q, off);
    float inv_std = rsqrtf(q * (1.0f / 63.0f));

    Out[(size_t)wid * 64 + lane]      = acc0 * inv_std;
    Out[(size_t)wid * 64 + lane + 32] = acc1 * inv_std;
}

// -------------------- launch --------------------
extern "C" void kernel_launch(void* const* d_in, const int* in_sizes, int n_in,
                              void* d_out, int out_size)
{
    const float* h   = (const float*)d_in[0];
    const int*   ei  = (const int*)d_in[1];
    const float* W11 = (const float*)d_in[2];
    const float* b11 = (const float*)d_in[3];
    const float* W12 = (const float*)d_in[4];
    const float* b12 = (const float*)d_in[5];
    const float* W13 = (const float*)d_in[6];
    const float* b13 = (const float*)d_in[7];
    const float* W21 = (const float*)d_in[8];
    const float* b21 = (const float*)d_in[9];
    const float* W22 = (const float*)d_in[10];
    const float* b22 = (const float*)d_in[11];
    const float* W23 = (const float*)d_in[12];
    const float* b23 = (const float*)d_in[13];

    int N = in_sizes[0] / 128;
    int E = in_sizes[1] / 2;
    const int* src = ei;
    const int* dst = ei + E;

    // scratch pointers (device symbols usable directly in kernels; get raw ptrs for outputs)
    float* a_dev;  cudaGetSymbolAddress((void**)&a_dev, g_a);
    float* v_dev;  cudaGetSymbolAddress((void**)&v_dev, g_v);
    float* h1_dev; cudaGetSymbolAddress((void**)&h1_dev, g_h1);

    // ---- build CSR ----
    k_zero_cnt<<<(N + 255) / 256, 256>>>(N);
    k_count<<<(E + 255) / 256, 256>>>(src, E);
    k_scan<<<1, 1024>>>(N, E);
    k_scatter<<<(E + 255) / 256, 256>>>(src, dst, E);

    int gemm_blocks = (N + BM - 1) / BM;
    int edge_blocks = (int)(((long long)E * 16 + 255) / 256);
    int agg_blocks = (int)(((long long)N * 32 + 255) / 256);

    // ---- layer 1 ----
    k_gemm<<<gemm_blocks, 256>>>(h, N, 128, W11, b11, a_dev);
    k_gemm<<<gemm_blocks, 256>>>(h, N, 128, W13, b13, v_dev);
    k_edge<<<edge_blocks, 256>>>(W12, b12, E);
    k_agg<<<agg_blocks, 256>>>(h1_dev, N);

    // ---- layer 2 ----
    k_gemm<<<gemm_blocks, 256>>>(h1_dev, N, 64, W21, b21, a_dev);
    k_gemm<<<gemm_blocks, 256>>>(h1_dev, N, 64, W23, b23, v_dev);
    k_edge<<<edge_blocks, 256>>>(W22, b22, E);
    k_agg<<<agg_blocks, 256>>>((float*)d_out, N);
}

// round 3
// speedup vs baseline: 2.3750x; 2.3750x over previous
#include <cuda_runtime.h>
#include <math.h>

// Problem capacities (fixed by the dataset: N=100000, E=1600000)
#define NMAX 100096
#define EMAX 1600000

// -------- scratch (alloc-free: __device__ globals) --------
__device__ float g_ps[NMAX];           // per-node edge-score scalar p[n] = tanh(xWa^T+ba)·We
__device__ float g_v[NMAX * 64];       // node values tanh(xWv^T+bv)
__device__ float g_h1[NMAX * 64];      // layer-1 output
__device__ float g_ex[EMAX];           // exp(edge logit), CSR order
__device__ int   g_rowptr[NMAX + 1];
__device__ int   g_cnt[NMAX];
__device__ int   g_dstc[EMAX];

// -------------------- CSR build --------------------
__global__ void k_zero_cnt(int N) {
    int i = blockIdx.x * blockDim.x + threadIdx.x;
    if (i < N) g_cnt[i] = 0;
}

__global__ void k_count(const int* __restrict__ src, int E) {
    int e = blockIdx.x * blockDim.x + threadIdx.x;
    if (e < E) atomicAdd(&g_cnt[src[e]], 1);
}

// single-block exclusive scan of g_cnt -> g_rowptr, zeroes g_cnt as it goes
__global__ void k_scan(int N, int E) {
    __shared__ int sh[1024];
    int t = threadIdx.x;
    int chunk = (N + 1023) / 1024;
    int start = t * chunk;
    int end = min(start + chunk, N);
    int s = 0;
    for (int i = start; i < end; i++) s += g_cnt[i];
    sh[t] = s;
    __syncthreads();
    for (int off = 1; off < 1024; off <<= 1) {
        int v = 0;
        if (t >= off) v = sh[t - off];
        __syncthreads();
        if (t >= off) sh[t] += v;
        __syncthreads();
    }
    int run = (t == 0) ? 0 : sh[t - 1];
    for (int i = start; i < end; i++) {
        int c = g_cnt[i];
        g_rowptr[i] = run;
        g_cnt[i] = 0;
        run += c;
    }
    if (t == 1023) g_rowptr[N] = sh[1023];  // == E
}

__global__ void k_scatter(const int* __restrict__ src, const int* __restrict__ dst, int E) {
    int e = blockIdx.x * blockDim.x + threadIdx.x;
    if (e < E) {
        int s = src[e];
        int p = g_rowptr[s] + atomicAdd(&g_cnt[s], 1);
        g_dstc[p] = dst[e];
    }
}

// -------------------- fused GEMM --------------------
// v[N,64]  = tanh(X[N,K] @ Wv^T + bv)
// ps[N]    = tanh(X[N,K] @ Wa^T + ba) · We       (per-node edge-score scalar)
#define BM 64
#define BK 16

__global__ __launch_bounds__(256) void k_gemm2(
    const float* __restrict__ X, int N, int K,
    const float* __restrict__ Wa, const float* __restrict__ ba,
    const float* __restrict__ We,
    const float* __restrict__ Wv, const float* __restrict__ bv,
    float* __restrict__ ps, float* __restrict__ v)
{
    __shared__ __align__(16) float Xs[BK][BM + 4];
    __shared__ __align__(16) float Was[BK][64 + 4];
    __shared__ __align__(16) float Wvs[BK][64 + 4];
    int tid = threadIdx.x;
    int bm = blockIdx.x * BM;
    int tr = tid / 16;       // 0..15
    int tc = tid % 16;       // 0..15
    int lm = tid / 4;        // 0..63
    int lk4 = (tid % 4) * 4; // 0,4,8,12

    float cV[4][4] = {};
    float cA[4][4] = {};

    for (int k0 = 0; k0 < K; k0 += BK) {
        {
            int gm = bm + lm;
            float4 q = make_float4(0.f, 0.f, 0.f, 0.f);
            if (gm < N) q = *(const float4*)&X[(size_t)gm * K + k0 + lk4];
            Xs[lk4 + 0][lm] = q.x; Xs[lk4 + 1][lm] = q.y;
            Xs[lk4 + 2][lm] = q.z; Xs[lk4 + 3][lm] = q.w;
        }
        {
            float4 q = *(const float4*)&Wa[(size_t)lm * K + k0 + lk4];
            Was[lk4 + 0][lm] = q.x; Was[lk4 + 1][lm] = q.y;
            Was[lk4 + 2][lm] = q.z; Was[lk4 + 3][lm] = q.w;
        }
        {
            float4 q = *(const float4*)&Wv[(size_t)lm * K + k0 + lk4];
            Wvs[lk4 + 0][lm] = q.x; Wvs[lk4 + 1][lm] = q.y;
            Wvs[lk4 + 2][lm] = q.z; Wvs[lk4 + 3][lm] = q.w;
        }
        __syncthreads();
        #pragma unroll
        for (int k = 0; k < BK; k++) {
            float a0[4], wa[4], wv[4];
            #pragma unroll
            for (int i = 0; i < 4; i++) a0[i] = Xs[k][tr * 4 + i];
            #pragma unroll
            for (int j = 0; j < 4; j++) { wa[j] = Was[k][tc * 4 + j]; wv[j] = Wvs[k][tc * 4 + j]; }
            #pragma unroll
            for (int i = 0; i < 4; i++)
                #pragma unroll
                for (int j = 0; j < 4; j++) {
                    cV[i][j] = fmaf(a0[i], wv[j], cV[i][j]);
                    cA[i][j] = fmaf(a0[i], wa[j], cA[i][j]);
                }
        }
        __syncthreads();
    }

    float we_r[4], ba_r[4], bv_r[4];
    #pragma unroll
    for (int j = 0; j < 4; j++) {
        int jj = tc * 4 + j;
        we_r[j] = We[jj]; ba_r[j] = ba[jj]; bv_r[j] = bv[jj];
    }

    #pragma unroll
    for (int i = 0; i < 4; i++) {
        float pacc = 0.f;
        float4 vv;
        float* vp = (float*)&vv;
        #pragma unroll
        for (int j = 0; j < 4; j++) {
            vp[j] = tanhf(cV[i][j] + bv_r[j]);
            pacc = fmaf(tanhf(cA[i][j] + ba_r[j]), we_r[j], pacc);
        }
        // reduce pacc across the 16 tc-lanes (uniform rows within each group)
        #pragma unroll
        for (int off = 8; off > 0; off >>= 1)
            pacc += __shfl_xor_sync(0xffffffffu, pacc, off);
        int gm = bm + tr * 4 + i;
        if (gm < N) {
            *(float4*)&v[(size_t)gm * 64 + tc * 4] = vv;
            if (tc == 0) ps[gm] = pacc;
        }
    }
}

// -------------------- fused softmax + aggregation + row std-norm (warp per node) ----
__global__ __launch_bounds__(256) void k_agg(
    const float* __restrict__ ps, const float* __restrict__ be,
    float* __restrict__ Out, int N)
{
    int wid = (blockIdx.x * blockDim.x + threadIdx.x) >> 5;
    int lane = threadIdx.x & 31;
    if (wid >= N) return;

    int r0 = g_rowptr[wid];
    int r1 = g_rowptr[wid + 1];
    float pr = ps[wid] + be[0];

    // pass 1: edge logits -> exp, softmax denominator
    float sum = 0.f;
    for (int p = r0 + lane; p < r1; p += 32) {
        int d = g_dstc[p];
        float e = expf(tanhf(pr + ps[d]));   // |tanh|<1 -> no max-subtraction needed
        g_ex[p] = e;
        sum += e;
    }
    #pragma unroll
    for (int off = 16; off > 0; off >>= 1) sum += __shfl_xor_sync(0xffffffffu, sum, off);
    float inv = 1.0f / sum;

    // pass 2: weighted gather of v rows
    float acc0 = 0.f, acc1 = 0.f;
    for (int base = r0; base < r1; base += 32) {
        int p = base + lane;
        float att = 0.f;
        int d = 0;
        if (p < r1) {
            att = g_ex[p] * inv;
            d = g_dstc[p];
        }
        int cnt = min(32, r1 - base);
        #pragma unroll 4
        for (int j = 0; j < cnt; j++) {
            float aj = __shfl_sync(0xffffffffu, att, j);
            int dj = __shfl_sync(0xffffffffu, d, j);
            acc0 = fmaf(aj, g_v[(size_t)dj * 64 + lane], acc0);
            acc1 = fmaf(aj, g_v[(size_t)dj * 64 + lane + 32], acc1);
        }
    }

    // unbiased row std-normalization over the 64 values
    float s = acc0 + acc1;
    #pragma unroll
    for (int off = 16; off > 0; off >>= 1) s += __shfl_xor_sync(0xffffffffu, s, off);
    float mean = s * (1.0f / 64.0f);
    float d0 = acc0 - mean, d1 = acc1 - mean;
    float q = d0 * d0 + d1 * d1;
    #pragma unroll
    for (int off = 16; off > 0; off >>= 1) q += __shfl_xor_sync(0xffffffffu, q, off);
    float inv_std = rsqrtf(q * (1.0f / 63.0f));

    Out[(size_t)wid * 64 + lane]      = acc0 * inv_std;
    Out[(size_t)wid * 64 + lane + 32] = acc1 * inv_std;
}

// -------------------- launch --------------------
extern "C" void kernel_launch(void* const* d_in, const int* in_sizes, int n_in,
                              void* d_out, int out_size)
{
    const float* h   = (const float*)d_in[0];
    const int*   ei  = (const int*)d_in[1];
    const float* W11 = (const float*)d_in[2];
    const float* b11 = (const float*)d_in[3];
    const float* W12 = (const float*)d_in[4];
    const float* b12 = (const float*)d_in[5];
    const float* W13 = (const float*)d_in[6];
    const float* b13 = (const float*)d_in[7];
    const float* W21 = (const float*)d_in[8];
    const float* b21 = (const float*)d_in[9];
    const float* W22 = (const float*)d_in[10];
    const float* b22 = (const float*)d_in[11];
    const float* W23 = (const float*)d_in[12];
    const float* b23 = (const float*)d_in[13];

    int N = in_sizes[0] / 128;
    int E = in_sizes[1] / 2;
    const int* src = ei;
    const int* dst = ei + E;

    float* ps_dev; cudaGetSymbolAddress((void**)&ps_dev, g_ps);
    float* v_dev;  cudaGetSymbolAddress((void**)&v_dev, g_v);
    float* h1_dev; cudaGetSymbolAddress((void**)&h1_dev, g_h1);

    // ---- build CSR ----
    k_zero_cnt<<<(N + 255) / 256, 256>>>(N);
    k_count<<<(E + 255) / 256, 256>>>(src, E);
    k_scan<<<1, 1024>>>(N, E);
    k_scatter<<<(E + 255) / 256, 256>>>(src, dst, E);

    int gemm_blocks = (N + BM - 1) / BM;
    int agg_blocks = (int)(((long long)N * 32 + 255) / 256);

    // ---- layer 1 ----
    k_gemm2<<<gemm_blocks, 256>>>(h, N, 128, W11, b11, W12, W13, b13, ps_dev, v_dev);
    k_agg<<<agg_blocks, 256>>>(ps_dev, b12, h1_dev, N);

    // ---- layer 2 ----
    k_gemm2<<<gemm_blocks, 256>>>(h1_dev, N, 64, W21, b21, W22, W23, b23, ps_dev, v_dev);
    k_agg<<<agg_blocks, 256>>>(ps_dev, b22, (float*)d_out, N);
}

// round 6
// speedup vs baseline: 2.4175x; 1.0179x over previous
#include <cuda_runtime.h>
#include <cuda_fp16.h>
#include <math.h>

// Problem capacities (fixed by the dataset: N=100000, E=1600000)
#define NMAX 100096
#define EMAX 1600000

// -------- scratch (alloc-free: __device__ globals) --------
__device__ float   g_ps[NMAX];          // per-node edge-score scalar p[n] = tanh(xWa^T+ba)·We
__device__ __half2 g_vh[NMAX * 32];     // node values tanh(xWv^T+bv), fp16, 64 cols = 32 half2
__device__ float   g_h1[NMAX * 64];     // layer-1 output (fp32, feeds layer-2 GEMM)
__device__ float   g_ex[EMAX];          // exp(edge logit), CSR order
__device__ int     g_rowptr[NMAX + 1];
__device__ int     g_cnt[NMAX];
__device__ int     g_dstc[EMAX];

// -------------------- CSR build --------------------
__global__ void k_count(const int* __restrict__ src, int E) {
    int e = blockIdx.x * blockDim.x + threadIdx.x;
    if (e < E) atomicAdd(&g_cnt[src[e]], 1);
}

// single-block exclusive scan of g_cnt -> g_rowptr, zeroes g_cnt as it goes
__global__ void k_scan(int N, int E) {
    __shared__ int sh[1024];
    int t = threadIdx.x;
    int chunk = (N + 1023) / 1024;
    int start = t * chunk;
    int end = min(start + chunk, N);
    int s = 0;
    for (int i = start; i < end; i++) s += g_cnt[i];
    sh[t] = s;
    __syncthreads();
    for (int off = 1; off < 1024; off <<= 1) {
        int v = 0;
        if (t >= off) v = sh[t - off];
        __syncthreads();
        if (t >= off) sh[t] += v;
        __syncthreads();
    }
    int run = (t == 0) ? 0 : sh[t - 1];
    for (int i = start; i < end; i++) {
        int c = g_cnt[i];
        g_rowptr[i] = run;
        g_cnt[i] = 0;
        run += c;
    }
    if (t == 1023) g_rowptr[N] = sh[1023];  // == E
}

__global__ void k_scatter(const int* __restrict__ src, const int* __restrict__ dst, int E) {
    int e = blockIdx.x * blockDim.x + threadIdx.x;
    if (e < E) {
        int s = src[e];
        int p = g_rowptr[s] + atomicAdd(&g_cnt[s], 1);
        g_dstc[p] = dst[e];
    }
}

// -------------------- fused GEMM --------------------
// vh[N,32] (half2) = tanh(X[N,K] @ Wv^T + bv)
// ps[N]            = tanh(X[N,K] @ Wa^T + ba) · We
#define BM 64
#define BK 16

__global__ __launch_bounds__(256) void k_gemm2(
    const float* __restrict__ X, int N, int K,
    const float* __restrict__ Wa, const float* __restrict__ ba,
    const float* __restrict__ We,
    const float* __restrict__ Wv, const float* __restrict__ bv,
    float* __restrict__ ps, __half2* __restrict__ vh)
{
    __shared__ __align__(16) float Xs[BK][BM + 4];
    __shared__ __align__(16) float Was[BK][64 + 4];
    __shared__ __align__(16) float Wvs[BK][64 + 4];
    int tid = threadIdx.x;
    int bm = blockIdx.x * BM;
    int tr = tid / 16;       // 0..15
    int tc = tid % 16;       // 0..15
    int lm = tid / 4;        // 0..63
    int lk4 = (tid % 4) * 4; // 0,4,8,12

    float cV[4][4] = {};
    float cA[4][4] = {};

    for (int k0 = 0; k0 < K; k0 += BK) {
        {
            int gm = bm + lm;
            float4 q = make_float4(0.f, 0.f, 0.f, 0.f);
            if (gm < N) q = *(const float4*)&X[(size_t)gm * K + k0 + lk4];
            Xs[lk4 + 0][lm] = q.x; Xs[lk4 + 1][lm] = q.y;
            Xs[lk4 + 2][lm] = q.z; Xs[lk4 + 3][lm] = q.w;
        }
        {
            float4 q = *(const float4*)&Wa[(size_t)lm * K + k0 + lk4];
            Was[lk4 + 0][lm] = q.x; Was[lk4 + 1][lm] = q.y;
            Was[lk4 + 2][lm] = q.z; Was[lk4 + 3][lm] = q.w;
        }
        {
            float4 q = *(const float4*)&Wv[(size_t)lm * K + k0 + lk4];
            Wvs[lk4 + 0][lm] = q.x; Wvs[lk4 + 1][lm] = q.y;
            Wvs[lk4 + 2][lm] = q.z; Wvs[lk4 + 3][lm] = q.w;
        }
        __syncthreads();
        #pragma unroll
        for (int k = 0; k < BK; k++) {
            float a0[4], wa[4], wv[4];
            #pragma unroll
            for (int i = 0; i < 4; i++) a0[i] = Xs[k][tr * 4 + i];
            #pragma unroll
            for (int j = 0; j < 4; j++) { wa[j] = Was[k][tc * 4 + j]; wv[j] = Wvs[k][tc * 4 + j]; }
            #pragma unroll
            for (int i = 0; i < 4; i++)
                #pragma unroll
                for (int j = 0; j < 4; j++) {
                    cV[i][j] = fmaf(a0[i], wv[j], cV[i][j]);
                    cA[i][j] = fmaf(a0[i], wa[j], cA[i][j]);
                }
        }
        __syncthreads();
    }

    float we_r[4], ba_r[4], bv_r[4];
    #pragma unroll
    for (int j = 0; j < 4; j++) {
        int jj = tc * 4 + j;
        we_r[j] = We[jj]; ba_r[j] = ba[jj]; bv_r[j] = bv[jj];
    }

    #pragma unroll
    for (int i = 0; i < 4; i++) {
        float pacc = 0.f;
        float vj[4];
        #pragma unroll
        for (int j = 0; j < 4; j++) {
            vj[j] = tanhf(cV[i][j] + bv_r[j]);
            pacc = fmaf(tanhf(cA[i][j] + ba_r[j]), we_r[j], pacc);
        }
        // reduce pacc across the 16 tc-lanes (uniform rows within each group)
        #pragma unroll
        for (int off = 8; off > 0; off >>= 1)
            pacc += __shfl_xor_sync(0xffffffffu, pacc, off);
        int gm = bm + tr * 4 + i;
        if (gm < N) {
            __half2 hv[2];
            hv[0] = __floats2half2_rn(vj[0], vj[1]);
            hv[1] = __floats2half2_rn(vj[2], vj[3]);
            *(uint2*)&vh[(size_t)gm * 32 + tc * 2] = *(uint2*)hv;
            if (tc == 0) ps[gm] = pacc;
        }
    }
}

// ---------- fused softmax + aggregation + row std-norm (warp per node) ----------
__global__ __launch_bounds__(256) void k_agg(
    const float* __restrict__ ps, const float* __restrict__ be,
    float* __restrict__ Out, int N)
{
    int wid = (blockIdx.x * blockDim.x + threadIdx.x) >> 5;
    int lane = threadIdx.x & 31;
    if (wid >= N) return;

    int r0 = g_rowptr[wid];
    int r1 = g_rowptr[wid + 1];
    float pr = ps[wid] + be[0];

    // pass 1: edge logits -> exp, softmax denominator
    float sum = 0.f;
    for (int p = r0 + lane; p < r1; p += 32) {
        int d = g_dstc[p];
        float e = expf(tanhf(pr + ps[d]));   // |tanh|<1 -> no max-subtraction needed
        g_ex[p] = e;
        sum += e;
    }
    #pragma unroll
    for (int off = 16; off > 0; off >>= 1) sum += __shfl_xor_sync(0xffffffffu, sum, off);
    float inv = 1.0f / sum;

    // pass 2: weighted gather of v rows (fp16, 128B/row)
    const __half2* vh = (const __half2*)g_vh;
    float acc0 = 0.f, acc1 = 0.f;   // cols lane*2, lane*2+1
    for (int base = r0; base < r1; base += 32) {
        int p = base + lane;
        float att = 0.f;
        int d = 0;
        if (p < r1) {
            att = g_ex[p] * inv;
            d = g_dstc[p];
        }
        int cnt = min(32, r1 - base);
        #pragma unroll 4
        for (int j = 0; j < cnt; j++) {
            float aj = __shfl_sync(0xffffffffu, att, j);
            int dj = __shfl_sync(0xffffffffu, d, j);
            float2 f = __half22float2(vh[(size_t)dj * 32 + lane]);
            acc0 = fmaf(aj, f.x, acc0);
            acc1 = fmaf(aj, f.y, acc1);
        }
    }

    // unbiased row std-normalization over the 64 values
    float s = acc0 + acc1;
    #pragma unroll
    for (int off = 16; off > 0; off >>= 1) s += __shfl_xor_sync(0xffffffffu, s, off);
    float mean = s * (1.0f / 64.0f);
    float d0 = acc0 - mean, d1 = acc1 - mean;
    float q = d0 * d0 + d1 * d1;
    #pragma unroll
    for (int off = 16; off > 0; off >>= 1) q += __shfl_xor_sync(0xffffffffu, q, off);
    float inv_std = rsqrtf(q * (1.0f / 63.0f));

    float2 o;
    o.x = acc0 * inv_std;
    o.y = acc1 * inv_std;
    *(float2*)&Out[(size_t)wid * 64 + lane * 2] = o;
}

// -------------------- launch --------------------
extern "C" void kernel_launch(void* const* d_in, const int* in_sizes, int n_in,
                              void* d_out, int out_size)
{
    const float* h   = (const float*)d_in[0];
    const int*   ei  = (const int*)d_in[1];
    const float* W11 = (const float*)d_in[2];
    const float* b11 = (const float*)d_in[3];
    const float* W12 = (const float*)d_in[4];
    const float* b12 = (const float*)d_in[5];
    const float* W13 = (const float*)d_in[6];
    const float* b13 = (const float*)d_in[7];
    const float* W21 = (const float*)d_in[8];
    const float* b21 = (const float*)d_in[9];
    const float* W22 = (const float*)d_in[10];
    const float* b22 = (const float*)d_in[11];
    const float* W23 = (const float*)d_in[12];
    const float* b23 = (const float*)d_in[13];

    int N = in_sizes[0] / 128;
    int E = in_sizes[1] / 2;
    const int* src = ei;
    const int* dst = ei + E;

    float*   ps_dev; cudaGetSymbolAddress((void**)&ps_dev, g_ps);
    __half2* vh_dev; cudaGetSymbolAddress((void**)&vh_dev, g_vh);
    float*   h1_dev; cudaGetSymbolAddress((void**)&h1_dev, g_h1);
    int*     cnt_dev; cudaGetSymbolAddress((void**)&cnt_dev, g_cnt);

    int gemm_blocks = (N + BM - 1) / BM;
    int agg_blocks = (int)(((long long)N * 32 + 255) / 256);

    // Side stream for the CSR build, overlapped with the layer-1 GEMM.
    // Created fresh every call (deterministic work); intentionally not destroyed:
    // destroying a capture-forked stream while capture is still active would
    // invalidate the capture, and kernel_launch is only invoked a couple of times.
    cudaStream_t s2;
    cudaStreamCreateWithFlags(&s2, cudaStreamNonBlocking);
    cudaEvent_t evFork, evJoin;
    cudaEventCreateWithFlags(&evFork, cudaEventDisableTiming);
    cudaEventCreateWithFlags(&evJoin, cudaEventDisableTiming);

    // fork: s2 branches off the main (capture) stream
    cudaEventRecord(evFork, 0);
    cudaStreamWaitEvent(s2, evFork, 0);

    // ---- CSR build on s2 ----
    cudaMemsetAsync(cnt_dev, 0, (size_t)N * sizeof(int), s2);
    k_count<<<(E + 255) / 256, 256, 0, s2>>>(src, E);
    k_scan<<<1, 1024, 0, s2>>>(N, E);
    k_scatter<<<(E + 255) / 256, 256, 0, s2>>>(src, dst, E);

    // ---- layer-1 GEMM on main stream (independent of CSR) ----
    k_gemm2<<<gemm_blocks, 256>>>(h, N, 128, W11, b11, W12, W13, b13, ps_dev, vh_dev);

    // join: main stream waits for CSR
    cudaEventRecord(evJoin, s2);
    cudaStreamWaitEvent(0, evJoin, 0);

    // ---- layer 1 aggregation ----
    k_agg<<<agg_blocks, 256>>>(ps_dev, b12, h1_dev, N);

    // ---- layer 2 ----
    k_gemm2<<<gemm_blocks, 256>>>(h1_dev, N, 64, W21, b21, W22, W23, b23, ps_dev, vh_dev);
    k_agg<<<agg_blocks, 256>>>(ps_dev, b22, (float*)d_out, N);
}

// round 7
// speedup vs baseline: 2.5311x; 1.0470x over previous
#include <cuda_runtime.h>
#include <cuda_fp16.h>
#include <math.h>

// Problem capacities (fixed by the dataset: N=100000, E=1600000)
#define NMAX 100096
#define EMAX 1600000

// -------- scratch (alloc-free: __device__ globals) --------
__device__ float   g_ps[NMAX];          // per-node edge-score scalar
__device__ __half2 g_vh[NMAX * 32];     // node values tanh(xWv^T+bv), fp16, 64 cols
__device__ float   g_h1[NMAX * 64];     // layer-1 output (fp32, feeds layer-2 GEMM)
__device__ float   g_ex[EMAX];          // exp(edge logit), CSR order
__device__ int     g_rowptr[NMAX + 1];
__device__ int     g_cnt[NMAX];
__device__ int     g_dstc[EMAX];

// -------------------- CSR build --------------------
__global__ void k_count(const int* __restrict__ src, int E) {
    int e = blockIdx.x * blockDim.x + threadIdx.x;
    if (e < E) atomicAdd(&g_cnt[src[e]], 1);
}

__global__ void k_scan(int N, int E) {
    __shared__ int sh[1024];
    int t = threadIdx.x;
    int chunk = (N + 1023) / 1024;
    int start = t * chunk;
    int end = min(start + chunk, N);
    int s = 0;
    for (int i = start; i < end; i++) s += g_cnt[i];
    sh[t] = s;
    __syncthreads();
    for (int off = 1; off < 1024; off <<= 1) {
        int v = 0;
        if (t >= off) v = sh[t - off];
        __syncthreads();
        if (t >= off) sh[t] += v;
        __syncthreads();
    }
    int run = (t == 0) ? 0 : sh[t - 1];
    for (int i = start; i < end; i++) {
        int c = g_cnt[i];
        g_rowptr[i] = run;
        g_cnt[i] = 0;
        run += c;
    }
    if (t == 1023) g_rowptr[N] = sh[1023];
}

__global__ void k_scatter(const int* __restrict__ src, const int* __restrict__ dst, int E) {
    int e = blockIdx.x * blockDim.x + threadIdx.x;
    if (e < E) {
        int s = src[e];
        int p = g_rowptr[s] + atomicAdd(&g_cnt[s], 1);
        g_dstc[p] = dst[e];
    }
}

// -------------------- fused GEMM (8-row register tile) --------------------
// vh[N,32] (half2) = tanh(X[N,K] @ Wv^T + bv)
// ps[N]            = tanh(X[N,K] @ Wa^T + ba) · We
#define BM 128
#define BK 16

__global__ __launch_bounds__(256) void k_gemm2(
    const float* __restrict__ X, int N, int K,
    const float* __restrict__ Wa, const float* __restrict__ ba,
    const float* __restrict__ We,
    const float* __restrict__ Wv, const float* __restrict__ bv,
    float* __restrict__ ps, __half2* __restrict__ vh)
{
    __shared__ __align__(16) float Xs[BK][BM];   // stride 512B: float4-aligned
    __shared__ __align__(16) float Was[BK][64];
    __shared__ __align__(16) float Wvs[BK][64];
    int tid = threadIdx.x;
    int bm = blockIdx.x * BM;
    int tr = tid >> 4;        // 0..15 : row group (8 rows each)
    int tc = tid & 15;        // 0..15 : col group (4 cols each)

    float cV[8][4] = {};
    float cA[8][4] = {};

    for (int k0 = 0; k0 < K; k0 += BK) {
        // load X tile: 128 rows x 16 k = 512 float4, 2 per thread
        #pragma unroll
        for (int j = 0; j < 2; j++) {
            int idx = tid + j * 256;
            int row = idx >> 2;
            int k4 = (idx & 3) * 4;
            int gm = bm + row;
            float4 q = make_float4(0.f, 0.f, 0.f, 0.f);
            if (gm < N) q = *(const float4*)&X[(size_t)gm * K + k0 + k4];
            Xs[k4 + 0][row] = q.x; Xs[k4 + 1][row] = q.y;
            Xs[k4 + 2][row] = q.z; Xs[k4 + 3][row] = q.w;
        }
        // load W tiles: 64 rows x 16 k = 256 float4 each, 1 per thread
        {
            int row = tid >> 2;
            int k4 = (tid & 3) * 4;
            float4 qa = *(const float4*)&Wa[(size_t)row * K + k0 + k4];
            Was[k4 + 0][row] = qa.x; Was[k4 + 1][row] = qa.y;
            Was[k4 + 2][row] = qa.z; Was[k4 + 3][row] = qa.w;
            float4 qv = *(const float4*)&Wv[(size_t)row * K + k0 + k4];
            Wvs[k4 + 0][row] = qv.x; Wvs[k4 + 1][row] = qv.y;
            Wvs[k4 + 2][row] = qv.z; Wvs[k4 + 3][row] = qv.w;
        }
        __syncthreads();
        #pragma unroll
        for (int k = 0; k < BK; k++) {
            float4 x0 = *(const float4*)&Xs[k][tr * 8];
            float4 x1 = *(const float4*)&Xs[k][tr * 8 + 4];
            float4 wa4 = *(const float4*)&Was[k][tc * 4];
            float4 wv4 = *(const float4*)&Wvs[k][tc * 4];
            float a0[8] = {x0.x, x0.y, x0.z, x0.w, x1.x, x1.y, x1.z, x1.w};
            float wa[4] = {wa4.x, wa4.y, wa4.z, wa4.w};
            float wv[4] = {wv4.x, wv4.y, wv4.z, wv4.w};
            #pragma unroll
            for (int i = 0; i < 8; i++)
                #pragma unroll
                for (int j = 0; j < 4; j++) {
                    cV[i][j] = fmaf(a0[i], wv[j], cV[i][j]);
                    cA[i][j] = fmaf(a0[i], wa[j], cA[i][j]);
                }
        }
        __syncthreads();
    }

    float we_r[4], ba_r[4], bv_r[4];
    #pragma unroll
    for (int j = 0; j < 4; j++) {
        int jj = tc * 4 + j;
        we_r[j] = We[jj]; ba_r[j] = ba[jj]; bv_r[j] = bv[jj];
    }

    #pragma unroll
    for (int i = 0; i < 8; i++) {
        float pacc = 0.f;
        float vj[4];
        #pragma unroll
        for (int j = 0; j < 4; j++) {
            vj[j] = tanhf(cV[i][j] + bv_r[j]);
            pacc = fmaf(tanhf(cA[i][j] + ba_r[j]), we_r[j], pacc);
        }
        #pragma unroll
        for (int off = 8; off > 0; off >>= 1)
            pacc += __shfl_xor_sync(0xffffffffu, pacc, off);
        int gm = bm + tr * 8 + i;
        if (gm < N) {
            __half2 hv[2];
            hv[0] = __floats2half2_rn(vj[0], vj[1]);
            hv[1] = __floats2half2_rn(vj[2], vj[3]);
            *(uint2*)&vh[(size_t)gm * 32 + tc * 2] = *(uint2*)hv;
            if (tc == 0) ps[gm] = pacc;
        }
    }
}

// ---------- fused softmax + aggregation + row std-norm (warp per node) ----------
// Pass 2: warp = 4 groups x 8 lanes. Group g handles edge base+g; lane loads a
// uint4 (8 fp16 columns) -> one LDG.128 per lane moves 4 full v rows per warp
// instruction, no shuffles in the loop.
__global__ __launch_bounds__(256) void k_agg(
    const float* __restrict__ ps, const float* __restrict__ be,
    float* __restrict__ Out, int N)
{
    int wid = (blockIdx.x * blockDim.x + threadIdx.x) >> 5;
    int lane = threadIdx.x & 31;
    if (wid >= N) return;

    int r0 = g_rowptr[wid];
    int r1 = g_rowptr[wid + 1];
    float pr = ps[wid] + be[0];

    // pass 1: edge logits -> exp, softmax denominator
    float sum = 0.f;
    for (int p = r0 + lane; p < r1; p += 32) {
        int d = g_dstc[p];
        float e = expf(tanhf(pr + ps[d]));   // |tanh|<1 -> no max-subtraction needed
        g_ex[p] = e;
        sum += e;
    }
    #pragma unroll
    for (int off = 16; off > 0; off >>= 1) sum += __shfl_xor_sync(0xffffffffu, sum, off);
    float inv = 1.0f / sum;

    // pass 2: 4 edges per warp-iteration
    int g = lane >> 3;    // 0..3  edge within group-of-4
    int c = lane & 7;     // 0..7  column chunk (8 cols)
    const uint4* v4 = (const uint4*)g_vh;    // row = 8 uint4 (64 fp16)
    float acc[8] = {};
    for (int base = r0; base < r1; base += 4) {
        int p = base + g;
        float att = 0.f;
        int d = 0;
        if (p < r1) {
            att = g_ex[p] * inv;    // 8-lane broadcast load, L1-hot
            d = g_dstc[p];
        }
        uint4 q = v4[(size_t)d * 8 + c];
        const __half2* hq = (const __half2*)&q;
        #pragma unroll
        for (int t = 0; t < 4; t++) {
            float2 f = __half22float2(hq[t]);
            acc[2 * t]     = fmaf(att, f.x, acc[2 * t]);
            acc[2 * t + 1] = fmaf(att, f.y, acc[2 * t + 1]);
        }
    }
    // reduce across the 4 edge-groups (lanes differing in bits 3,4)
    #pragma unroll
    for (int t = 0; t < 8; t++) {
        acc[t] += __shfl_xor_sync(0xffffffffu, acc[t], 8);
        acc[t] += __shfl_xor_sync(0xffffffffu, acc[t], 16);
    }

    // row stats over 64 cols: butterfly across c bits only (g copies identical)
    float s = 0.f;
    #pragma unroll
    for (int t = 0; t < 8; t++) s += acc[t];
    #pragma unroll
    for (int off = 4; off > 0; off >>= 1) s += __shfl_xor_sync(0xffffffffu, s, off);
    float mean = s * (1.0f / 64.0f);
    float q2 = 0.f;
    #pragma unroll
    for (int t = 0; t < 8; t++) { float dq = acc[t] - mean; q2 = fmaf(dq, dq, q2); }
    #pragma unroll
    for (int off = 4; off > 0; off >>= 1) q2 += __shfl_xor_sync(0xffffffffu, q2, off);
    float inv_std = rsqrtf(q2 * (1.0f / 63.0f));

    // write: groups 0,1 write the two float4 halves of chunk c
    if (g < 2) {
        float4 o;
        o.x = acc[g * 4 + 0] * inv_std;
        o.y = acc[g * 4 + 1] * inv_std;
        o.z = acc[g * 4 + 2] * inv_std;
        o.w = acc[g * 4 + 3] * inv_std;
        *(float4*)&Out[(size_t)wid * 64 + c * 8 + g * 4] = o;
    }
}

// -------------------- launch --------------------
extern "C" void kernel_launch(void* const* d_in, const int* in_sizes, int n_in,
                              void* d_out, int out_size)
{
    const float* h   = (const float*)d_in[0];
    const int*   ei  = (const int*)d_in[1];
    const float* W11 = (const float*)d_in[2];
    const float* b11 = (const float*)d_in[3];
    const float* W12 = (const float*)d_in[4];
    const float* b12 = (const float*)d_in[5];
    const float* W13 = (const float*)d_in[6];
    const float* b13 = (const float*)d_in[7];
    const float* W21 = (const float*)d_in[8];
    const float* b21 = (const float*)d_in[9];
    const float* W22 = (const float*)d_in[10];
    const float* b22 = (const float*)d_in[11];
    const float* W23 = (const float*)d_in[12];
    const float* b23 = (const float*)d_in[13];

    int N = in_sizes[0] / 128;
    int E = in_sizes[1] / 2;
    const int* src = ei;
    const int* dst = ei + E;

    float*   ps_dev; cudaGetSymbolAddress((void**)&ps_dev, g_ps);
    __half2* vh_dev; cudaGetSymbolAddress((void**)&vh_dev, g_vh);
    float*   h1_dev; cudaGetSymbolAddress((void**)&h1_dev, g_h1);
    int*     cnt_dev; cudaGetSymbolAddress((void**)&cnt_dev, g_cnt);

    int gemm_blocks = (N + BM - 1) / BM;
    int agg_blocks = (int)(((long long)N * 32 + 255) / 256);

    // Side stream: CSR build overlapped with the layer-1 GEMM (fork/join off
    // the capture stream). Streams/events intentionally leaked (host-side only;
    // destroying a capture-forked stream mid-capture would invalidate it).
    cudaStream_t s2;
    cudaStreamCreateWithFlags(&s2, cudaStreamNonBlocking);
    cudaEvent_t evFork, evJoin;
    cudaEventCreateWithFlags(&evFork, cudaEventDisableTiming);
    cudaEventCreateWithFlags(&evJoin, cudaEventDisableTiming);

    cudaEventRecord(evFork, 0);
    cudaStreamWaitEvent(s2, evFork, 0);

    // ---- CSR build on s2 ----
    cudaMemsetAsync(cnt_dev, 0, (size_t)N * sizeof(int), s2);
    k_count<<<(E + 255) / 256, 256, 0, s2>>>(src, E);
    k_scan<<<1, 1024, 0, s2>>>(N, E);
    k_scatter<<<(E + 255) / 256, 256, 0, s2>>>(src, dst, E);

    // ---- layer-1 GEMM on main stream (independent of CSR) ----
    k_gemm2<<<gemm_blocks, 256>>>(h, N, 128, W11, b11, W12, W13, b13, ps_dev, vh_dev);

    cudaEventRecord(evJoin, s2);
    cudaStreamWaitEvent(0, evJoin, 0);

    // ---- layer 1 aggregation ----
    k_agg<<<agg_blocks, 256>>>(ps_dev, b12, h1_dev, N);

    // ---- layer 2 ----
    k_gemm2<<<gemm_blocks, 256>>>(h1_dev, N, 64, W21, b21, W22, W23, b23, ps_dev, vh_dev);
    k_agg<<<agg_blocks, 256>>>(ps_dev, b22, (float*)d_out, N);
}